// round 1
// baseline (speedup 1.0000x reference)
#include <cuda_runtime.h>
#include <math.h>

#define Bb   128
#define Nn   49
#define Dd   2048
#define H1v  1024
#define H2v  512
#define ROWS (Bb*Nn)   // 6272
#define TOPKv 20

// ---------------- scratch (static device memory; no allocation) ----------------
__device__ float g_h1a[ROWS*H1v];
__device__ float g_h1b[ROWS*H1v];
__device__ float g_h2a[ROWS*H2v];
__device__ float g_h2b[ROWS*H2v];
__device__ float g_s1 [ROWS*Dd];
__device__ float g_part[(size_t)Bb*Nn*Nn];
__device__ float g_scores[Nn*Nn];
__device__ float g_M[Nn*Nn];
__device__ float g_bnsc[4*Nn];
__device__ float g_bnsh[4*Nn];
__device__ float g_rowsum[2*H2v];
__device__ float g_topv[2*Nn*TOPKv];
__device__ int   g_topi[2*Nn*TOPKv];

// ---------------- helpers ----------------
__device__ __forceinline__ float blockReduceSum(float v)
{
    __shared__ float sbuf[32];
    int lane = threadIdx.x & 31;
    int w    = threadIdx.x >> 5;
    #pragma unroll
    for (int o = 16; o > 0; o >>= 1) v += __shfl_down_sync(0xffffffffu, v, o);
    __syncthreads();                 // protect sbuf from previous use
    if (lane == 0) sbuf[w] = v;
    __syncthreads();
    int nw = (blockDim.x + 31) >> 5;
    float tot = 0.f;
    #pragma unroll
    for (int i = 0; i < 8; i++) if (i < nw) tot += sbuf[i];
    return tot;                      // deterministic, same value in all threads
}

// ---------------- SGEMM: C = relu(epilogue(A @ W^T)) ----------------
// A: (M,K) row-major, W: (Nc,K) row-major. Optional fused BN affine on A:
//   C[r,o] = relu( sc[r%49]*acc + sh[r%49]*rowsum[o] + bias[o] )
struct GemmArgs {
    const float* A; const float* W; const float* bias;
    const float* bnscale; const float* bnshift; const float* rowsum;
    float* C;
};

__global__ __launch_bounds__(256, 2)
void sgemm_kernel(GemmArgs ga0, GemmArgs ga1, int Nc, int K)
{
    GemmArgs g = (blockIdx.z == 0) ? ga0 : ga1;
    __shared__ float As[8][128];
    __shared__ float Bs[8][128];
    const int bm = blockIdx.y * 128;
    const int bn = blockIdx.x * 128;
    const int tid  = threadIdx.x;
    const int warp = tid >> 5, lane = tid & 31;
    const int mBase = (warp >> 1) * 32 + (lane >> 3) * 4;   // rows: +{0..3,16..19}
    const int nBase = (warp & 1) * 64 + (lane & 7) * 4;     // cols: +{0..3,32..35}

    float acc[8][8];
    #pragma unroll
    for (int i = 0; i < 8; i++)
        #pragma unroll
        for (int j = 0; j < 8; j++) acc[i][j] = 0.f;

    const int lr = tid >> 1;
    const int ls = (tid & 1) * 4;
    const float* Ap = g.A + (size_t)(bm + lr) * K + ls;
    const float* Wp = g.W + (size_t)(bn + lr) * K + ls;

    for (int k0 = 0; k0 < K; k0 += 8) {
        float4 av = *(const float4*)(Ap + k0);
        float4 wv = *(const float4*)(Wp + k0);
        __syncthreads();
        As[ls+0][lr] = av.x; As[ls+1][lr] = av.y; As[ls+2][lr] = av.z; As[ls+3][lr] = av.w;
        Bs[ls+0][lr] = wv.x; Bs[ls+1][lr] = wv.y; Bs[ls+2][lr] = wv.z; Bs[ls+3][lr] = wv.w;
        __syncthreads();
        #pragma unroll
        for (int kk = 0; kk < 8; kk++) {
            float ra[8], rb[8];
            *(float4*)(ra)     = *(const float4*)&As[kk][mBase];
            *(float4*)(ra + 4) = *(const float4*)&As[kk][mBase + 16];
            *(float4*)(rb)     = *(const float4*)&Bs[kk][nBase];
            *(float4*)(rb + 4) = *(const float4*)&Bs[kk][nBase + 32];
            #pragma unroll
            for (int i = 0; i < 8; i++)
                #pragma unroll
                for (int j = 0; j < 8; j++)
                    acc[i][j] += ra[i] * rb[j];
        }
    }

    float bcol[8], rs[8];
    #pragma unroll
    for (int j = 0; j < 8; j++) {
        int col = bn + nBase + (j & 3) + (j >> 2) * 32;
        bcol[j] = g.bias[col];
        rs[j]   = g.rowsum ? g.rowsum[col] : 0.f;
    }
    #pragma unroll
    for (int i = 0; i < 8; i++) {
        int row = bm + mBase + (i & 3) + (i >> 2) * 16;
        float sc = 1.f, sh = 0.f;
        if (g.bnscale) { int n = row % Nn; sc = g.bnscale[n]; sh = g.bnshift[n]; }
        float v[8];
        #pragma unroll
        for (int j = 0; j < 8; j++)
            v[j] = fmaxf(sc * acc[i][j] + sh * rs[j] + bcol[j], 0.f);
        float* Cp = g.C + (size_t)row * Nc + bn + nBase;
        *(float4*)(Cp)      = make_float4(v[0], v[1], v[2], v[3]);
        *(float4*)(Cp + 32) = make_float4(v[4], v[5], v[6], v[7]);
    }
}

// ---------------- rowsum of W over K (for folded BN shift) ----------------
__global__ void rowsum_kernel(const float* W0, const float* W1, int K, float* out)
{
    int o = blockIdx.x, s = blockIdx.y;
    const float* W = s ? W1 : W0;
    float sum = 0.f;
    for (int k = threadIdx.x; k < K; k += blockDim.x) sum += W[(size_t)o * K + k];
    sum = blockReduceSum(sum);
    if (threadIdx.x == 0) out[s * H2v + o] = sum;
}

// ---------------- BN stats per n over (B, O): scale/shift affine ----------------
__global__ void bnstats_kernel(const float* hA, const float* hB, int O,
                               const float* gA, const float* beA,
                               const float* gB, const float* beB,
                               float* sc, float* sh)
{
    int n = blockIdx.x, s = blockIdx.y;
    const float* h  = s ? hB : hA;
    const float* gg = s ? gB : gA;
    const float* be = s ? beB : beA;
    float sum = 0.f, ss = 0.f;
    for (int b = 0; b < Bb; b++) {
        const float* row = h + (size_t)(b * Nn + n) * O;
        for (int o = threadIdx.x; o < O; o += blockDim.x) {
            float v = row[o]; sum += v; ss += v * v;
        }
    }
    sum = blockReduceSum(sum);
    ss  = blockReduceSum(ss);
    if (threadIdx.x == 0) {
        float cnt  = (float)Bb * (float)O;
        float mean = sum / cnt;
        float var  = ss / cnt - mean * mean;
        float r    = rsqrtf(var + 1e-5f);
        float scale = gg[n] * r;
        sc[s * Nn + n] = scale;
        sh[s * Nn + n] = be[n] - mean * scale;
    }
}

// ---------------- scores partial: part[b,n,m] = sum_h f1[b,n,h]*f2[b,m,h] ----------------
// f applied on-the-fly: f = sc*h2 + sh (layer-b BN affine)
__global__ void scores_part_kernel(const float* h2a, const float* h2b,
                                   const float* sc, const float* sh, float* part)
{
    int b = blockIdx.x;
    __shared__ float As[Nn][65];
    __shared__ float Bs[Nn][65];
    int tid = threadIdx.x;
    int tx = tid & 15, ty = tid >> 4;
    float acc[4][4];
    #pragma unroll
    for (int i = 0; i < 4; i++)
        #pragma unroll
        for (int j = 0; j < 4; j++) acc[i][j] = 0.f;

    for (int h0 = 0; h0 < H2v; h0 += 64) {
        __syncthreads();
        for (int idx = tid; idx < Nn * 64; idx += 256) {
            int n = idx >> 6, kk = idx & 63;
            As[n][kk] = sc[2*Nn+n] * h2a[(size_t)(b*Nn+n)*H2v + h0 + kk] + sh[2*Nn+n];
            Bs[n][kk] = sc[3*Nn+n] * h2b[(size_t)(b*Nn+n)*H2v + h0 + kk] + sh[3*Nn+n];
        }
        __syncthreads();
        for (int kk = 0; kk < 64; kk++) {
            float ra[4], rb[4];
            #pragma unroll
            for (int i = 0; i < 4; i++) {
                int n = ty + 16 * i; ra[i] = (n < Nn) ? As[n][kk] : 0.f;
                int m = tx + 16 * i; rb[i] = (m < Nn) ? Bs[m][kk] : 0.f;
            }
            #pragma unroll
            for (int i = 0; i < 4; i++)
                #pragma unroll
                for (int j = 0; j < 4; j++)
                    acc[i][j] += ra[i] * rb[j];
        }
    }
    #pragma unroll
    for (int i = 0; i < 4; i++)
        #pragma unroll
        for (int j = 0; j < 4; j++) {
            int n = ty + 16 * i, m = tx + 16 * j;
            if (n < Nn && m < Nn)
                part[(size_t)b * Nn * Nn + n * Nn + m] = acc[i][j];
        }
}

__global__ void scores_reduce_kernel(const float* part, float* scores)
{
    int nm = blockIdx.x * 256 + threadIdx.x;
    if (nm >= Nn * Nn) return;
    float s = 0.f;
    for (int b = 0; b < Bb; b++) s += part[(size_t)b * Nn * Nn + nm];
    scores[nm] = s;
}

// ---------------- M = vmat + tanh(scores @ wlin^T + blin) ----------------
__global__ void mlin_kernel(const float* scores, const float* wlin, const float* blin,
                            const float* vmat, float* Mout)
{
    int n = blockIdx.x;
    __shared__ float srow[Nn];
    if (threadIdx.x < Nn) srow[threadIdx.x] = scores[n * Nn + threadIdx.x];
    __syncthreads();
    int j = threadIdx.x;
    if (j < Nn) {
        float acc = blin[j];
        for (int m = 0; m < Nn; m++) acc += srow[m] * wlin[j * Nn + m];
        Mout[n * Nn + j] = vmat[n * Nn + j] + tanhf(acc);
    }
}

// ---------------- softmax (full) + top-20 selection; mode0=rows of M, mode1=cols ----------------
__global__ void topk_kernel(const float* M, float* vout, int* iout)
{
    int mode = blockIdx.x, t = threadIdx.x;
    if (t >= Nn) return;
    float p[Nn];
    float mx = -1e30f;
    for (int i = 0; i < Nn; i++) {
        float val = (mode == 0) ? M[t * Nn + i] : M[i * Nn + t];
        p[i] = val; mx = fmaxf(mx, val);
    }
    float sum = 0.f;
    for (int i = 0; i < Nn; i++) { p[i] = expf(p[i] - mx); sum += p[i]; }
    float inv = 1.f / sum;
    for (int i = 0; i < Nn; i++) p[i] *= inv;
    for (int k = 0; k < TOPKv; k++) {
        float bv = -1.f; int bi = 0;
        for (int i = 0; i < Nn; i++)
            if (p[i] > bv) { bv = p[i]; bi = i; }   // strict > : lowest index wins ties (jax)
        vout[mode * Nn * TOPKv + t * TOPKv + k] = bv;
        iout[mode * Nn * TOPKv + t * TOPKv + k] = bi;
        p[bi] = -2.f;
    }
}

// ---------------- fusion (gather + weighted sum) fused with LayerNorm ----------------
// x = base[b,n,:] + sum_k v[n,k] * gath[b, ind[n,k], :]
// optionally store raw x to s1_out; always write LN(x) to out row (b, rowOff+n)
__global__ __launch_bounds__(256)
void fusion_kernel(const float* base, const float* gath,
                   const float* vsel, const int* isel,
                   const float* ln_g, const float* ln_b,
                   float* s1_out, float* out, int rowOff)
{
    int n = blockIdx.x, b = blockIdx.y, tid = threadIdx.x;
    __shared__ float sv[TOPKv];
    __shared__ int   si[TOPKv];
    if (tid < TOPKv) { sv[tid] = vsel[n * TOPKv + tid]; si[tid] = isel[n * TOPKv + tid]; }
    __syncthreads();

    size_t rbase = (size_t)(b * Nn + n) * Dd;
    float x[8];
    #pragma unroll
    for (int i = 0; i < 8; i++) x[i] = base[rbase + i * 256 + tid];
    for (int k = 0; k < TOPKv; k++) {
        float w = sv[k];
        const float* gp = gath + (size_t)(b * Nn + si[k]) * Dd + tid;
        #pragma unroll
        for (int i = 0; i < 8; i++) x[i] += w * gp[i * 256];
    }
    if (s1_out) {
        #pragma unroll
        for (int i = 0; i < 8; i++) s1_out[rbase + i * 256 + tid] = x[i];
    }
    float s = 0.f, ss = 0.f;
    #pragma unroll
    for (int i = 0; i < 8; i++) { s += x[i]; ss += x[i] * x[i]; }
    s  = blockReduceSum(s);
    ss = blockReduceSum(ss);
    float mean = s * (1.f / Dd);
    float var  = fmaxf((ss - s * mean) * (1.f / (Dd - 1)), 0.f);  // ddof=1
    float inv  = 1.f / (sqrtf(var) + 1e-6f);                      // (std + eps)!
    size_t obase = (size_t)(b * (2 * Nn) + rowOff + n) * Dd;
    #pragma unroll
    for (int i = 0; i < 8; i++) {
        int d = i * 256 + tid;
        out[obase + d] = ln_g[d] * (x[i] - mean) * inv + ln_b[d];
    }
}

// ---------------- host launcher ----------------
extern "C" void kernel_launch(void* const* d_in, const int* in_sizes, int n_in,
                              void* d_out, int out_size)
{
    const float* src1 = (const float*)d_in[0];
    const float* src2 = (const float*)d_in[1];
    const float* w0a  = (const float*)d_in[2];
    const float* b0a  = (const float*)d_in[3];
    const float* g0a  = (const float*)d_in[4];
    const float* be0a = (const float*)d_in[5];
    const float* w0b  = (const float*)d_in[6];
    const float* b0b  = (const float*)d_in[7];
    const float* g0b  = (const float*)d_in[8];
    const float* be0b = (const float*)d_in[9];
    const float* w1a  = (const float*)d_in[10];
    const float* b1a  = (const float*)d_in[11];
    const float* g1a  = (const float*)d_in[12];
    const float* be1a = (const float*)d_in[13];
    const float* w1b  = (const float*)d_in[14];
    const float* b1b  = (const float*)d_in[15];
    const float* g1b  = (const float*)d_in[16];
    const float* be1b = (const float*)d_in[17];
    const float* wlin = (const float*)d_in[18];
    const float* blin = (const float*)d_in[19];
    const float* ln_g = (const float*)d_in[20];
    const float* ln_b = (const float*)d_in[21];
    const float* vmat = (const float*)d_in[22];
    float* out = (float*)d_out;

    void* p;
    float *h1a, *h1b, *h2a, *h2b, *s1, *part, *scores, *Mbuf, *bnsc, *bnsh, *rsum, *topv;
    int* topi;
    cudaGetSymbolAddress(&p, g_h1a);    h1a    = (float*)p;
    cudaGetSymbolAddress(&p, g_h1b);    h1b    = (float*)p;
    cudaGetSymbolAddress(&p, g_h2a);    h2a    = (float*)p;
    cudaGetSymbolAddress(&p, g_h2b);    h2b    = (float*)p;
    cudaGetSymbolAddress(&p, g_s1);     s1     = (float*)p;
    cudaGetSymbolAddress(&p, g_part);   part   = (float*)p;
    cudaGetSymbolAddress(&p, g_scores); scores = (float*)p;
    cudaGetSymbolAddress(&p, g_M);      Mbuf   = (float*)p;
    cudaGetSymbolAddress(&p, g_bnsc);   bnsc   = (float*)p;
    cudaGetSymbolAddress(&p, g_bnsh);   bnsh   = (float*)p;
    cudaGetSymbolAddress(&p, g_rowsum); rsum   = (float*)p;
    cudaGetSymbolAddress(&p, g_topv);   topv   = (float*)p;
    cudaGetSymbolAddress(&p, g_topi);   topi   = (int*)p;

    // Layer 1: h1 = relu(src @ w_a^T + b_a), both streams in one launch
    GemmArgs ga0 = { src1, w0a, b0a, nullptr, nullptr, nullptr, h1a };
    GemmArgs ga1 = { src2, w1a, b1a, nullptr, nullptr, nullptr, h1b };
    sgemm_kernel<<<dim3(H1v / 128, ROWS / 128, 2), 256>>>(ga0, ga1, H1v, Dd);

    // rowsums of second-layer weights (for folded BN shift)
    rowsum_kernel<<<dim3(H2v, 2), 256>>>(w0b, w1b, H1v, rsum);

    // BN stats layer a
    bnstats_kernel<<<dim3(Nn, 2), 256>>>(h1a, h1b, H1v, g0a, be0a, g1a, be1a, bnsc, bnsh);

    // Layer 2 with folded layer-a BN affine: h2 = relu(sc*(h1@w_b^T) + sh*rowsum + b_b)
    GemmArgs gb0 = { h1a, w0b, b0b, bnsc,       bnsh,       rsum,        h2a };
    GemmArgs gb1 = { h1b, w1b, b1b, bnsc + Nn,  bnsh + Nn,  rsum + H2v,  h2b };
    sgemm_kernel<<<dim3(H2v / 128, ROWS / 128, 2), 256>>>(gb0, gb1, H2v, H1v);

    // BN stats layer b (affine applied inside scores kernel)
    bnstats_kernel<<<dim3(Nn, 2), 256>>>(h2a, h2b, H2v, g0b, be0b, g1b, be1b,
                                         bnsc + 2 * Nn, bnsh + 2 * Nn);

    // scores[n,m] = sum_{b,d} f1 f2  (deterministic two-stage reduction)
    scores_part_kernel<<<Bb, 256>>>(h2a, h2b, bnsc, bnsh, part);
    scores_reduce_kernel<<<(Nn * Nn + 255) / 256, 256>>>(part, scores);

    // M = vmat + tanh(scores @ wlin^T + blin)
    mlin_kernel<<<Nn, 64>>>(scores, wlin, blin, vmat, Mbuf);

    // softmax + top-20 for rows (mode 0) and columns (mode 1)
    topk_kernel<<<2, 64>>>(Mbuf, topv, topi);

    // s1 = src1 + gather(src2); store raw s1, write LN(s1) to out rows [0,49)
    fusion_kernel<<<dim3(Nn, Bb), 256>>>(src1, src2, topv, topi,
                                         ln_g, ln_b, s1, out, 0);
    // s2 = src2 + gather(s1); write LN(s2) to out rows [49,98)
    fusion_kernel<<<dim3(Nn, Bb), 256>>>(src2, s1, topv + Nn * TOPKv, topi + Nn * TOPKv,
                                         ln_g, ln_b, nullptr, out, Nn);
}

// round 2
// speedup vs baseline: 1.0422x; 1.0422x over previous
#include <cuda_runtime.h>
#include <math.h>

#define Bb   128
#define Nn   49
#define Dd   2048
#define H1v  1024
#define H2v  512
#define ROWS (Bb*Nn)   // 6272
#define TOPKv 20

// ---------------- scratch (static device memory; no allocation) ----------------
__device__ float g_h1a[ROWS*H1v];
__device__ float g_h1b[ROWS*H1v];
__device__ float g_h2a[ROWS*H2v];
__device__ float g_h2b[ROWS*H2v];
__device__ float g_s1 [ROWS*Dd];
__device__ float g_part[(size_t)Bb*Nn*Nn];
__device__ float g_scores[Nn*Nn];
__device__ float g_M[Nn*Nn];
__device__ float g_bnsc[4*Nn];
__device__ float g_bnsh[4*Nn];
__device__ float g_rowsum[2*H2v];
__device__ float g_topv[2*Nn*TOPKv];
__device__ int   g_topi[2*Nn*TOPKv];

// ---------------- helpers ----------------
__device__ __forceinline__ float blockReduceSum(float v)
{
    __shared__ float sbuf[32];
    int lane = threadIdx.x & 31;
    int w    = threadIdx.x >> 5;
    #pragma unroll
    for (int o = 16; o > 0; o >>= 1) v += __shfl_down_sync(0xffffffffu, v, o);
    __syncthreads();                 // protect sbuf from previous use
    if (lane == 0) sbuf[w] = v;
    __syncthreads();
    int nw = (blockDim.x + 31) >> 5;
    float tot = 0.f;
    #pragma unroll
    for (int i = 0; i < 8; i++) if (i < nw) tot += sbuf[i];
    return tot;                      // deterministic, same value in all threads
}

// ---------------- SGEMM: C = relu(epilogue(A @ W^T)) ----------------
// A: (M,K) row-major, W: (Nc,K) row-major. Optional fused BN affine on A:
//   C[r,o] = relu( sc[r%49]*acc + sh[r%49]*rowsum[o] + bias[o] )
struct GemmArgs {
    const float* A; const float* W; const float* bias;
    const float* bnscale; const float* bnshift; const float* rowsum;
    float* C;
};

__global__ __launch_bounds__(256, 2)
void sgemm_kernel(GemmArgs ga0, GemmArgs ga1, int Nc, int K)
{
    GemmArgs g = (blockIdx.z == 0) ? ga0 : ga1;
    __shared__ float As[8][128];
    __shared__ float Bs[8][128];
    const int bm = blockIdx.y * 128;
    const int bn = blockIdx.x * 128;
    const int tid  = threadIdx.x;
    const int warp = tid >> 5, lane = tid & 31;
    const int mBase = (warp >> 1) * 32 + (lane >> 3) * 4;   // rows: +{0..3,16..19}
    const int nBase = (warp & 1) * 64 + (lane & 7) * 4;     // cols: +{0..3,32..35}

    float acc[8][8];
    #pragma unroll
    for (int i = 0; i < 8; i++)
        #pragma unroll
        for (int j = 0; j < 8; j++) acc[i][j] = 0.f;

    const int lr = tid >> 1;
    const int ls = (tid & 1) * 4;
    const float* Ap = g.A + (size_t)(bm + lr) * K + ls;
    const float* Wp = g.W + (size_t)(bn + lr) * K + ls;

    for (int k0 = 0; k0 < K; k0 += 8) {
        float4 av = *(const float4*)(Ap + k0);
        float4 wv = *(const float4*)(Wp + k0);
        __syncthreads();
        As[ls+0][lr] = av.x; As[ls+1][lr] = av.y; As[ls+2][lr] = av.z; As[ls+3][lr] = av.w;
        Bs[ls+0][lr] = wv.x; Bs[ls+1][lr] = wv.y; Bs[ls+2][lr] = wv.z; Bs[ls+3][lr] = wv.w;
        __syncthreads();
        #pragma unroll
        for (int kk = 0; kk < 8; kk++) {
            float ra[8], rb[8];
            *(float4*)(ra)     = *(const float4*)&As[kk][mBase];
            *(float4*)(ra + 4) = *(const float4*)&As[kk][mBase + 16];
            *(float4*)(rb)     = *(const float4*)&Bs[kk][nBase];
            *(float4*)(rb + 4) = *(const float4*)&Bs[kk][nBase + 32];
            #pragma unroll
            for (int i = 0; i < 8; i++)
                #pragma unroll
                for (int j = 0; j < 8; j++)
                    acc[i][j] += ra[i] * rb[j];
        }
    }

    float bcol[8], rs[8];
    #pragma unroll
    for (int j = 0; j < 8; j++) {
        int col = bn + nBase + (j & 3) + (j >> 2) * 32;
        bcol[j] = g.bias[col];
        rs[j]   = g.rowsum ? g.rowsum[col] : 0.f;
    }
    #pragma unroll
    for (int i = 0; i < 8; i++) {
        int row = bm + mBase + (i & 3) + (i >> 2) * 16;
        float sc = 1.f, sh = 0.f;
        if (g.bnscale) { int n = row % Nn; sc = g.bnscale[n]; sh = g.bnshift[n]; }
        float v[8];
        #pragma unroll
        for (int j = 0; j < 8; j++)
            v[j] = fmaxf(sc * acc[i][j] + sh * rs[j] + bcol[j], 0.f);
        float* Cp = g.C + (size_t)row * Nc + bn + nBase;
        *(float4*)(Cp)      = make_float4(v[0], v[1], v[2], v[3]);
        *(float4*)(Cp + 32) = make_float4(v[4], v[5], v[6], v[7]);
    }
}

// ---------------- rowsum of W over K (for folded BN shift) ----------------
__global__ void rowsum_kernel(const float* W0, const float* W1, int K, float* out)
{
    int o = blockIdx.x, s = blockIdx.y;
    const float* W = s ? W1 : W0;
    float sum = 0.f;
    for (int k = threadIdx.x; k < K; k += blockDim.x) sum += W[(size_t)o * K + k];
    sum = blockReduceSum(sum);
    if (threadIdx.x == 0) out[s * H2v + o] = sum;
}

// ---------------- BN stats per n over (B, O): scale/shift affine ----------------
__global__ void bnstats_kernel(const float* hA, const float* hB, int O,
                               const float* gA, const float* beA,
                               const float* gB, const float* beB,
                               float* sc, float* sh)
{
    int n = blockIdx.x, s = blockIdx.y;
    const float* h  = s ? hB : hA;
    const float* gg = s ? gB : gA;
    const float* be = s ? beB : beA;
    float sum = 0.f, ss = 0.f;
    for (int b = 0; b < Bb; b++) {
        const float* row = h + (size_t)(b * Nn + n) * O;
        for (int o = threadIdx.x; o < O; o += blockDim.x) {
            float v = row[o]; sum += v; ss += v * v;
        }
    }
    sum = blockReduceSum(sum);
    ss  = blockReduceSum(ss);
    if (threadIdx.x == 0) {
        float cnt  = (float)Bb * (float)O;
        float mean = sum / cnt;
        float var  = ss / cnt - mean * mean;
        float r    = rsqrtf(var + 1e-5f);
        float scale = gg[n] * r;
        sc[s * Nn + n] = scale;
        sh[s * Nn + n] = be[n] - mean * scale;
    }
}

// ---------------- scores partial: part[b,n,m] = sum_h f1[b,n,h]*f2[b,m,h] ----------------
// f applied on-the-fly: f = sc*h2 + sh (layer-b BN affine)
__global__ void scores_part_kernel(const float* h2a, const float* h2b,
                                   const float* sc, const float* sh, float* part)
{
    int b = blockIdx.x;
    __shared__ float As[Nn][65];
    __shared__ float Bs[Nn][65];
    int tid = threadIdx.x;
    int tx = tid & 15, ty = tid >> 4;
    float acc[4][4];
    #pragma unroll
    for (int i = 0; i < 4; i++)
        #pragma unroll
        for (int j = 0; j < 4; j++) acc[i][j] = 0.f;

    for (int h0 = 0; h0 < H2v; h0 += 64) {
        __syncthreads();
        for (int idx = tid; idx < Nn * 64; idx += 256) {
            int n = idx >> 6, kk = idx & 63;
            As[n][kk] = sc[2*Nn+n] * h2a[(size_t)(b*Nn+n)*H2v + h0 + kk] + sh[2*Nn+n];
            Bs[n][kk] = sc[3*Nn+n] * h2b[(size_t)(b*Nn+n)*H2v + h0 + kk] + sh[3*Nn+n];
        }
        __syncthreads();
        for (int kk = 0; kk < 64; kk++) {
            float ra[4], rb[4];
            #pragma unroll
            for (int i = 0; i < 4; i++) {
                int n = ty + 16 * i; ra[i] = (n < Nn) ? As[n][kk] : 0.f;
                int m = tx + 16 * i; rb[i] = (m < Nn) ? Bs[m][kk] : 0.f;
            }
            #pragma unroll
            for (int i = 0; i < 4; i++)
                #pragma unroll
                for (int j = 0; j < 4; j++)
                    acc[i][j] += ra[i] * rb[j];
        }
    }
    #pragma unroll
    for (int i = 0; i < 4; i++)
        #pragma unroll
        for (int j = 0; j < 4; j++) {
            int n = ty + 16 * i, m = tx + 16 * j;
            if (n < Nn && m < Nn)
                part[(size_t)b * Nn * Nn + n * Nn + m] = acc[i][j];
        }
}

__global__ void scores_reduce_kernel(const float* part, float* scores)
{
    int nm = blockIdx.x * 256 + threadIdx.x;
    if (nm >= Nn * Nn) return;
    float s = 0.f;
    for (int b = 0; b < Bb; b++) s += part[(size_t)b * Nn * Nn + nm];
    scores[nm] = s;
}

// ---------------- M = vmat + tanh(scores @ wlin^T + blin) ----------------
__global__ void mlin_kernel(const float* scores, const float* wlin, const float* blin,
                            const float* vmat, float* Mout)
{
    int n = blockIdx.x;
    __shared__ float srow[Nn];
    if (threadIdx.x < Nn) srow[threadIdx.x] = scores[n * Nn + threadIdx.x];
    __syncthreads();
    int j = threadIdx.x;
    if (j < Nn) {
        float acc = blin[j];
        for (int m = 0; m < Nn; m++) acc += srow[m] * wlin[j * Nn + m];
        Mout[n * Nn + j] = vmat[n * Nn + j] + tanhf(acc);
    }
}

// ---------------- softmax (full) + top-20 selection; mode0=rows of M, mode1=cols ----------------
__global__ void topk_kernel(const float* M, float* vout, int* iout)
{
    int mode = blockIdx.x, t = threadIdx.x;
    if (t >= Nn) return;
    float p[Nn];
    float mx = -1e30f;
    for (int i = 0; i < Nn; i++) {
        float val = (mode == 0) ? M[t * Nn + i] : M[i * Nn + t];
        p[i] = val; mx = fmaxf(mx, val);
    }
    float sum = 0.f;
    for (int i = 0; i < Nn; i++) { p[i] = expf(p[i] - mx); sum += p[i]; }
    float inv = 1.f / sum;
    for (int i = 0; i < Nn; i++) p[i] *= inv;
    for (int k = 0; k < TOPKv; k++) {
        float bv = -1.f; int bi = 0;
        for (int i = 0; i < Nn; i++)
            if (p[i] > bv) { bv = p[i]; bi = i; }   // strict > : lowest index wins ties (jax)
        vout[mode * Nn * TOPKv + t * TOPKv + k] = bv;
        iout[mode * Nn * TOPKv + t * TOPKv + k] = bi;
        p[bi] = -2.f;
    }
}

// ---------------- fusion (gather + weighted sum) fused with LayerNorm ----------------
// x = base[b,n,:] + sum_k v[n,k] * gath[b, ind[n,k], :]
// optionally store raw x to s1_out; always write LN(x) to out row (b, rowOff+n)
__global__ __launch_bounds__(256)
void fusion_kernel(const float* base, const float* gath,
                   const float* vsel, const int* isel,
                   const float* ln_g, const float* ln_b,
                   float* s1_out, float* out, int rowOff)
{
    int n = blockIdx.x, b = blockIdx.y, tid = threadIdx.x;
    __shared__ float sv[TOPKv];
    __shared__ int   si[TOPKv];
    if (tid < TOPKv) { sv[tid] = vsel[n * TOPKv + tid]; si[tid] = isel[n * TOPKv + tid]; }
    __syncthreads();

    size_t rbase = (size_t)(b * Nn + n) * Dd;
    float x[8];
    #pragma unroll
    for (int i = 0; i < 8; i++) x[i] = base[rbase + i * 256 + tid];
    for (int k = 0; k < TOPKv; k++) {
        float w = sv[k];
        const float* gp = gath + (size_t)(b * Nn + si[k]) * Dd + tid;
        #pragma unroll
        for (int i = 0; i < 8; i++) x[i] += w * gp[i * 256];
    }
    if (s1_out) {
        #pragma unroll
        for (int i = 0; i < 8; i++) s1_out[rbase + i * 256 + tid] = x[i];
    }
    float s = 0.f, ss = 0.f;
    #pragma unroll
    for (int i = 0; i < 8; i++) { s += x[i]; ss += x[i] * x[i]; }
    s  = blockReduceSum(s);
    ss = blockReduceSum(ss);
    float mean = s * (1.f / Dd);
    float var  = fmaxf((ss - s * mean) * (1.f / (Dd - 1)), 0.f);  // ddof=1
    float inv  = 1.f / (sqrtf(var) + 1e-6f);                      // (std + eps)!
    size_t obase = (size_t)(b * (2 * Nn) + rowOff + n) * Dd;
    #pragma unroll
    for (int i = 0; i < 8; i++) {
        int d = i * 256 + tid;
        out[obase + d] = ln_g[d] * (x[i] - mean) * inv + ln_b[d];
    }
}

// ---------------- host launcher ----------------
extern "C" void kernel_launch(void* const* d_in, const int* in_sizes, int n_in,
                              void* d_out, int out_size)
{
    const float* src1 = (const float*)d_in[0];
    const float* src2 = (const float*)d_in[1];
    const float* w0a  = (const float*)d_in[2];
    const float* b0a  = (const float*)d_in[3];
    const float* g0a  = (const float*)d_in[4];
    const float* be0a = (const float*)d_in[5];
    const float* w0b  = (const float*)d_in[6];
    const float* b0b  = (const float*)d_in[7];
    const float* g0b  = (const float*)d_in[8];
    const float* be0b = (const float*)d_in[9];
    const float* w1a  = (const float*)d_in[10];
    const float* b1a  = (const float*)d_in[11];
    const float* g1a  = (const float*)d_in[12];
    const float* be1a = (const float*)d_in[13];
    const float* w1b  = (const float*)d_in[14];
    const float* b1b  = (const float*)d_in[15];
    const float* g1b  = (const float*)d_in[16];
    const float* be1b = (const float*)d_in[17];
    const float* wlin = (const float*)d_in[18];
    const float* blin = (const float*)d_in[19];
    const float* ln_g = (const float*)d_in[20];
    const float* ln_b = (const float*)d_in[21];
    const float* vmat = (const float*)d_in[22];
    float* out = (float*)d_out;

    void* p;
    float *h1a, *h1b, *h2a, *h2b, *s1, *part, *scores, *Mbuf, *bnsc, *bnsh, *rsum, *topv;
    int* topi;
    cudaGetSymbolAddress(&p, g_h1a);    h1a    = (float*)p;
    cudaGetSymbolAddress(&p, g_h1b);    h1b    = (float*)p;
    cudaGetSymbolAddress(&p, g_h2a);    h2a    = (float*)p;
    cudaGetSymbolAddress(&p, g_h2b);    h2b    = (float*)p;
    cudaGetSymbolAddress(&p, g_s1);     s1     = (float*)p;
    cudaGetSymbolAddress(&p, g_part);   part   = (float*)p;
    cudaGetSymbolAddress(&p, g_scores); scores = (float*)p;
    cudaGetSymbolAddress(&p, g_M);      Mbuf   = (float*)p;
    cudaGetSymbolAddress(&p, g_bnsc);   bnsc   = (float*)p;
    cudaGetSymbolAddress(&p, g_bnsh);   bnsh   = (float*)p;
    cudaGetSymbolAddress(&p, g_rowsum); rsum   = (float*)p;
    cudaGetSymbolAddress(&p, g_topv);   topv   = (float*)p;
    cudaGetSymbolAddress(&p, g_topi);   topi   = (int*)p;

    // Layer 1: h1 = relu(src @ w_a^T + b_a), both streams in one launch
    GemmArgs ga0 = { src1, w0a, b0a, nullptr, nullptr, nullptr, h1a };
    GemmArgs ga1 = { src2, w1a, b1a, nullptr, nullptr, nullptr, h1b };
    sgemm_kernel<<<dim3(H1v / 128, ROWS / 128, 2), 256>>>(ga0, ga1, H1v, Dd);

    // rowsums of second-layer weights (for folded BN shift)
    rowsum_kernel<<<dim3(H2v, 2), 256>>>(w0b, w1b, H1v, rsum);

    // BN stats layer a
    bnstats_kernel<<<dim3(Nn, 2), 256>>>(h1a, h1b, H1v, g0a, be0a, g1a, be1a, bnsc, bnsh);

    // Layer 2 with folded layer-a BN affine: h2 = relu(sc*(h1@w_b^T) + sh*rowsum + b_b)
    GemmArgs gb0 = { h1a, w0b, b0b, bnsc,       bnsh,       rsum,        h2a };
    GemmArgs gb1 = { h1b, w1b, b1b, bnsc + Nn,  bnsh + Nn,  rsum + H2v,  h2b };
    sgemm_kernel<<<dim3(H2v / 128, ROWS / 128, 2), 256>>>(gb0, gb1, H2v, H1v);

    // BN stats layer b (affine applied inside scores kernel)
    bnstats_kernel<<<dim3(Nn, 2), 256>>>(h2a, h2b, H2v, g0b, be0b, g1b, be1b,
                                         bnsc + 2 * Nn, bnsh + 2 * Nn);

    // scores[n,m] = sum_{b,d} f1 f2  (deterministic two-stage reduction)
    scores_part_kernel<<<Bb, 256>>>(h2a, h2b, bnsc, bnsh, part);
    scores_reduce_kernel<<<(Nn * Nn + 255) / 256, 256>>>(part, scores);

    // M = vmat + tanh(scores @ wlin^T + blin)
    mlin_kernel<<<Nn, 64>>>(scores, wlin, blin, vmat, Mbuf);

    // softmax + top-20 for rows (mode 0) and columns (mode 1)
    topk_kernel<<<2, 64>>>(Mbuf, topv, topi);

    // s1 = src1 + gather(src2); store raw s1, write LN(s1) to out rows [0,49)
    fusion_kernel<<<dim3(Nn, Bb), 256>>>(src1, src2, topv, topi,
                                         ln_g, ln_b, s1, out, 0);
    // s2 = src2 + gather(s1); write LN(s2) to out rows [49,98)
    fusion_kernel<<<dim3(Nn, Bb), 256>>>(src2, s1, topv + Nn * TOPKv, topi + Nn * TOPKv,
                                         ln_g, ln_b, nullptr, out, Nn);
}

// round 4
// speedup vs baseline: 1.8559x; 1.7808x over previous
#include <cuda_runtime.h>
#include <cuda_bf16.h>
#include <math.h>
#include <stdint.h>

#define Bb 128
#define Nn 49
#define Dd 2048
#define H1v 1024
#define H2v 512
#define ROWS (Bb*Nn)
#define TOPKv 20

typedef __nv_bfloat16 bf16;

// ---------------- static scratch ----------------
__device__ alignas(128) bf16 g_x1e[(size_t)ROWS*3*Dd];   // src1 ext [hi|hi|lo]
__device__ alignas(128) bf16 g_x2e[(size_t)ROWS*3*Dd];
__device__ alignas(128) bf16 g_w0ae[(size_t)H1v*3*Dd];   // W ext [hi|lo|hi]
__device__ alignas(128) bf16 g_w1ae[(size_t)H1v*3*Dd];
__device__ alignas(128) bf16 g_w0be[(size_t)H2v*3*H1v];
__device__ alignas(128) bf16 g_w1be[(size_t)H2v*3*H1v];
__device__ alignas(128) bf16 g_h1ae[(size_t)ROWS*3*H1v]; // h1 ext [hi|hi|lo]
__device__ alignas(128) bf16 g_h1be[(size_t)ROWS*3*H1v];
__device__ alignas(128) float g_h2a[ROWS*H2v], g_h2b[ROWS*H2v];
__device__ alignas(128) float g_s1[ROWS*Dd];
__device__ float g_part[(size_t)Bb*Nn*Nn], g_scores[Nn*Nn], g_M[Nn*Nn];
__device__ float g_bnsc[4*Nn], g_bnsh[4*Nn], g_rowsum[2*H2v];
__device__ float g_topv[2*Nn*TOPKv];
__device__ int   g_topi[2*Nn*TOPKv];

// ---------------- PTX helpers (sm_80-class; compile on plain sm_103 target) ----------------
__device__ __forceinline__ uint32_t smem_u32(const void* p) {
    uint32_t a;
    asm("{ .reg .u64 t; cvta.to.shared.u64 t, %1; cvt.u32.u64 %0, t; }" : "=r"(a) : "l"(p));
    return a;
}
__device__ __forceinline__ void cp16(uint32_t s, const void* g) {
    asm volatile("cp.async.cg.shared.global [%0], [%1], 16;" :: "r"(s), "l"(g));
}
#define CP_COMMIT() asm volatile("cp.async.commit_group;" ::: "memory")
#define CP_WAIT2()  asm volatile("cp.async.wait_group 2;" ::: "memory")

__device__ __forceinline__ void ldsm_x4(uint32_t (&r)[4], uint32_t a) {
    asm volatile("ldmatrix.sync.aligned.m8n8.x4.shared.b16 {%0,%1,%2,%3}, [%4];"
        : "=r"(r[0]), "=r"(r[1]), "=r"(r[2]), "=r"(r[3]) : "r"(a));
}
__device__ __forceinline__ void ldsm_x2(uint32_t (&r)[2], uint32_t a) {
    asm volatile("ldmatrix.sync.aligned.m8n8.x2.shared.b16 {%0,%1}, [%2];"
        : "=r"(r[0]), "=r"(r[1]) : "r"(a));
}
__device__ __forceinline__ void hmma(float (&d)[4], const uint32_t (&a)[4], const uint32_t (&b)[2]) {
    asm volatile("mma.sync.aligned.m16n8k16.row.col.f32.bf16.bf16.f32 "
        "{%0,%1,%2,%3},{%4,%5,%6,%7},{%8,%9},{%0,%1,%2,%3};"
        : "+f"(d[0]), "+f"(d[1]), "+f"(d[2]), "+f"(d[3])
        : "r"(a[0]), "r"(a[1]), "r"(a[2]), "r"(a[3]), "r"(b[0]), "r"(b[1]));
}
__device__ __forceinline__ uint32_t packbf2(float a, float b) {
    __nv_bfloat162 t = __floats2bfloat162_rn(a, b);
    return *reinterpret_cast<uint32_t*>(&t);
}

__device__ __forceinline__ float blockReduceSum(float v) {
    __shared__ float sb[32];
    int lane = threadIdx.x & 31, w = threadIdx.x >> 5;
    #pragma unroll
    for (int o = 16; o > 0; o >>= 1) v += __shfl_down_sync(0xffffffffu, v, o);
    __syncthreads();
    if (lane == 0) sb[w] = v;
    __syncthreads();
    int nw = (blockDim.x + 31) >> 5;
    float t = 0.f;
    #pragma unroll
    for (int i = 0; i < 8; i++) if (i < nw) t += sb[i];
    return t;
}

// ---------------- fp32 -> extended bf16 layout ----------------
// kindA=1: [hi | hi | lo];  kindA=0 (B/weights): [hi | lo | hi]
__global__ void cvt_ext(const float* __restrict__ x, bf16* __restrict__ y, int K4, int n4, int kindA) {
    int i = blockIdx.x * blockDim.x + threadIdx.x;
    if (i >= n4) return;
    int row = i / K4, k4 = i - row * K4;
    float4 v = reinterpret_cast<const float4*>(x)[i];
    bf16 h0 = __float2bfloat16(v.x), h1 = __float2bfloat16(v.y);
    bf16 h2 = __float2bfloat16(v.z), h3 = __float2bfloat16(v.w);
    uint2 hw, lw;
    hw.x = packbf2(v.x, v.y); hw.y = packbf2(v.z, v.w);
    lw.x = packbf2(v.x - __bfloat162float(h0), v.y - __bfloat162float(h1));
    lw.y = packbf2(v.z - __bfloat162float(h2), v.w - __bfloat162float(h3));
    bf16* base = y + (size_t)row * (12 * K4) + k4 * 4;
    *reinterpret_cast<uint2*>(base) = hw;
    if (kindA) {
        *reinterpret_cast<uint2*>(base + 4 * K4) = hw;
        *reinterpret_cast<uint2*>(base + 8 * K4) = lw;
    } else {
        *reinterpret_cast<uint2*>(base + 4 * K4) = lw;
        *reinterpret_cast<uint2*>(base + 8 * K4) = hw;
    }
}

// ---------------- HMMA GEMM over ext K: C = relu(epi(A @ W^T)) ----------------
// mode 0: write Cext (bf16, [hi|hi|lo] over Nc), epi = acc + bias[col]
// mode 1: write Cf (fp32), epi = sc[row%49]*acc + sh[row%49]*rs[col] + bias[col]
struct GArgs {
    const bf16 *A, *W;
    const float *bias, *bnsc, *bnsh, *rs;
    float* Cf; bf16* Cext;
};

__global__ __launch_bounds__(256, 1)
void hmma_gemm(GArgs ga0, GArgs ga1, int Nc, int Kext, int nch, int mode)
{
    extern __shared__ char dsm[];
    GArgs g = blockIdx.z ? ga1 : ga0;
    const int tid = threadIdx.x, lane = tid & 31, warp = tid >> 5;
    const int warpM = warp >> 2, warpN = warp & 3;        // 2 x 4 warps
    const int bm = blockIdx.y * 128, bn = blockIdx.x * 128;
    const uint32_t sbase = smem_u32(dsm);

    const bf16* Ag = g.A + (size_t)bm * Kext;
    const bf16* Wg = g.W + (size_t)bn * Kext;

    // cp.async assignments: 4 chunks of A + 4 of W per thread per stage
    int cRow[4], cSw[4];
    #pragma unroll
    for (int i = 0; i < 4; i++) {
        int idx = i * 256 + tid;
        int r = idx >> 3, c16 = idx & 7;
        cRow[i] = r;
        int off = r * 128 + c16 * 16;
        cSw[i] = off ^ ((r & 7) << 4);
    }

    // ldmatrix address precompute
    const int la = lane & 15;
    const uint32_t khA = (lane >> 4) * 16;
    uint32_t aAdd[4], aX[4];
    #pragma unroll
    for (int mi = 0; mi < 4; mi++) {
        int r = warpM * 64 + mi * 16 + la;
        aAdd[mi] = r * 128; aX[mi] = (r & 7) << 4;
    }
    const uint32_t khB = ((lane >> 3) & 1) * 16;
    uint32_t bAdd[4], bX[4];
    #pragma unroll
    for (int nj = 0; nj < 4; nj++) {
        int r = warpN * 32 + nj * 8 + (lane & 7);
        bAdd[nj] = r * 128; bX[nj] = (r & 7) << 4;
    }

    float acc[4][4][4];
    #pragma unroll
    for (int mi = 0; mi < 4; mi++)
        #pragma unroll
        for (int nj = 0; nj < 4; nj++)
            #pragma unroll
            for (int q = 0; q < 4; q++) acc[mi][nj][q] = 0.f;

    auto load_chunk = [&](int c, int stage) {
        if (c < nch) {
            uint32_t sA = sbase + stage * 32768u;
            const int kofs = c * 64;
            #pragma unroll
            for (int i = 0; i < 4; i++) {
                cp16(sA + cSw[i],          Ag + (size_t)cRow[i] * Kext + kofs + (cSw[i] == cSw[i] ? 0 : 0) + ((i*256+tid) & 7) * 8);
            }
            #pragma unroll
            for (int i = 0; i < 4; i++) {
                cp16(sA + 16384u + cSw[i], Wg + (size_t)cRow[i] * Kext + kofs + ((i*256+tid) & 7) * 8);
            }
        }
        CP_COMMIT();
    };
    // NOTE: the A-load line above must use the same c16 math; rewrite cleanly:
    // (lambda re-done below without the placeholder)

    auto load_chunk2 = [&](int c, int stage) {
        if (c < nch) {
            uint32_t sA = sbase + stage * 32768u;
            const int kofs = c * 64;
            #pragma unroll
            for (int i = 0; i < 4; i++) {
                int idx = i * 256 + tid;
                int c16 = idx & 7;
                cp16(sA + cSw[i],          Ag + (size_t)cRow[i] * Kext + kofs + c16 * 8);
                cp16(sA + 16384u + cSw[i], Wg + (size_t)cRow[i] * Kext + kofs + c16 * 8);
            }
        }
        CP_COMMIT();
    };
    (void)load_chunk;

    load_chunk2(0, 0);
    load_chunk2(1, 1);

    for (int c = 0; c < nch; c++) {
        load_chunk2(c + 2, (c + 2) % 3);
        CP_WAIT2();
        __syncthreads();
        uint32_t sA = sbase + (uint32_t)(c % 3) * 32768u;
        uint32_t sW = sA + 16384u;
        #pragma unroll
        for (int ks = 0; ks < 4; ks++) {
            uint32_t afr[4][4], bfr[4][2];
            #pragma unroll
            for (int mi = 0; mi < 4; mi++)
                ldsm_x4(afr[mi], sA + aAdd[mi] + (((uint32_t)ks * 32 + khA) ^ aX[mi]));
            #pragma unroll
            for (int nj = 0; nj < 4; nj++)
                ldsm_x2(bfr[nj], sW + bAdd[nj] + (((uint32_t)ks * 32 + khB) ^ bX[nj]));
            #pragma unroll
            for (int mi = 0; mi < 4; mi++)
                #pragma unroll
                for (int nj = 0; nj < 4; nj++)
                    hmma(acc[mi][nj], afr[mi], bfr[nj]);
        }
        __syncthreads();
    }

    // ---------------- epilogue ----------------
    const int gq = lane >> 2, tq = lane & 3;
    #pragma unroll
    for (int mi = 0; mi < 4; mi++) {
        #pragma unroll
        for (int nj = 0; nj < 4; nj++) {
            int co = bn + warpN * 32 + nj * 8 + tq * 2;
            float bia0 = g.bias[co], bia1 = g.bias[co + 1];
            float rs0 = 0.f, rs1 = 0.f;
            if (mode == 1) { rs0 = g.rs[co]; rs1 = g.rs[co + 1]; }
            #pragma unroll
            for (int half = 0; half < 2; half++) {
                int row = bm + warpM * 64 + mi * 16 + gq + half * 8;
                float a0 = acc[mi][nj][2 * half], a1 = acc[mi][nj][2 * half + 1];
                if (mode == 1) {
                    int n = row % Nn;
                    float sc = g.bnsc[n], sh = g.bnsh[n];
                    float v0 = fmaxf(sc * a0 + sh * rs0 + bia0, 0.f);
                    float v1 = fmaxf(sc * a1 + sh * rs1 + bia1, 0.f);
                    *reinterpret_cast<float2*>(g.Cf + (size_t)row * Nc + co) = make_float2(v0, v1);
                } else {
                    float v0 = fmaxf(a0 + bia0, 0.f);
                    float v1 = fmaxf(a1 + bia1, 0.f);
                    bf16 h0 = __float2bfloat16(v0), h1 = __float2bfloat16(v1);
                    uint32_t hw = packbf2(v0, v1);
                    uint32_t lw = packbf2(v0 - __bfloat162float(h0), v1 - __bfloat162float(h1));
                    uint32_t* Crow = reinterpret_cast<uint32_t*>(g.Cext + (size_t)row * (3 * Nc));
                    Crow[co >> 1] = hw;
                    Crow[(Nc + co) >> 1] = hw;
                    Crow[(2 * Nc + co) >> 1] = lw;
                }
            }
        }
    }
}

// ---------------- rowsum of W over K ----------------
__global__ void rowsum_kernel(const float* W0, const float* W1, int K, float* out) {
    int o = blockIdx.x, s = blockIdx.y;
    const float* W = s ? W1 : W0;
    float sum = 0.f;
    for (int k = threadIdx.x; k < K; k += blockDim.x) sum += W[(size_t)o * K + k];
    sum = blockReduceSum(sum);
    if (threadIdx.x == 0) out[s * H2v + o] = sum;
}

// ---------------- BN stats per n over (B,O) on ext bf16 (hi at col k, lo at 2K+k) ----------------
__global__ void bnstats_ext(const bf16* hA, const bf16* hB, int O,
                            const float* gA, const float* beA,
                            const float* gB, const float* beB, float* sc, float* sh) {
    int n = blockIdx.x, s = blockIdx.y;
    const bf16* h = s ? hB : hA;
    const float* gg = s ? gB : gA;
    const float* be = s ? beB : beA;
    float sum = 0.f, ss = 0.f;
    for (int b = 0; b < Bb; b++) {
        size_t off = (size_t)(b * Nn + n) * (3 * O);
        const __nv_bfloat162* ph = reinterpret_cast<const __nv_bfloat162*>(h + off);
        const __nv_bfloat162* pl = reinterpret_cast<const __nv_bfloat162*>(h + off + 2 * O);
        for (int o = threadIdx.x; o < O / 2; o += blockDim.x) {
            __nv_bfloat162 a = ph[o], c = pl[o];
            float v0 = __bfloat162float(a.x) + __bfloat162float(c.x);
            float v1 = __bfloat162float(a.y) + __bfloat162float(c.y);
            sum += v0 + v1; ss += v0 * v0 + v1 * v1;
        }
    }
    sum = blockReduceSum(sum); ss = blockReduceSum(ss);
    if (threadIdx.x == 0) {
        float cnt = (float)Bb * O, mean = sum / cnt;
        float var = ss / cnt - mean * mean;
        float scale = gg[n] * rsqrtf(var + 1e-5f);
        sc[s * Nn + n] = scale; sh[s * Nn + n] = be[n] - mean * scale;
    }
}

// ---------------- BN stats fp32 (layer b, on h2) ----------------
__global__ void bnstats_f32(const float* hA, const float* hB, int O,
                            const float* gA, const float* beA,
                            const float* gB, const float* beB, float* sc, float* sh) {
    int n = blockIdx.x, s = blockIdx.y;
    const float* h = s ? hB : hA;
    const float* gg = s ? gB : gA;
    const float* be = s ? beB : beA;
    float sum = 0.f, ss = 0.f;
    for (int b = 0; b < Bb; b++) {
        const float* row = h + (size_t)(b * Nn + n) * O;
        for (int o = threadIdx.x; o < O; o += blockDim.x) { float v = row[o]; sum += v; ss += v * v; }
    }
    sum = blockReduceSum(sum); ss = blockReduceSum(ss);
    if (threadIdx.x == 0) {
        float cnt = (float)Bb * O, mean = sum / cnt;
        float var = ss / cnt - mean * mean;
        float scale = gg[n] * rsqrtf(var + 1e-5f);
        sc[s * Nn + n] = scale; sh[s * Nn + n] = be[n] - mean * scale;
    }
}

// ---------------- scores ----------------
__global__ void scores_part_kernel(const float* h2a, const float* h2b,
                                   const float* sc, const float* sh, float* part) {
    int b = blockIdx.x;
    __shared__ float As[Nn][65], Bs[Nn][65];
    int tid = threadIdx.x, tx = tid & 15, ty = tid >> 4;
    float acc[4][4];
    #pragma unroll
    for (int i = 0; i < 4; i++)
        #pragma unroll
        for (int j = 0; j < 4; j++) acc[i][j] = 0.f;
    for (int h0 = 0; h0 < H2v; h0 += 64) {
        __syncthreads();
        for (int idx = tid; idx < Nn * 64; idx += 256) {
            int n = idx >> 6, kk = idx & 63;
            As[n][kk] = sc[2*Nn+n] * h2a[(size_t)(b*Nn+n)*H2v + h0 + kk] + sh[2*Nn+n];
            Bs[n][kk] = sc[3*Nn+n] * h2b[(size_t)(b*Nn+n)*H2v + h0 + kk] + sh[3*Nn+n];
        }
        __syncthreads();
        for (int kk = 0; kk < 64; kk++) {
            float ra[4], rb[4];
            #pragma unroll
            for (int i = 0; i < 4; i++) {
                int n = ty + 16 * i; ra[i] = (n < Nn) ? As[n][kk] : 0.f;
                int m = tx + 16 * i; rb[i] = (m < Nn) ? Bs[m][kk] : 0.f;
            }
            #pragma unroll
            for (int i = 0; i < 4; i++)
                #pragma unroll
                for (int j = 0; j < 4; j++) acc[i][j] += ra[i] * rb[j];
        }
    }
    #pragma unroll
    for (int i = 0; i < 4; i++)
        #pragma unroll
        for (int j = 0; j < 4; j++) {
            int n = ty + 16 * i, m = tx + 16 * j;
            if (n < Nn && m < Nn) part[(size_t)b * Nn * Nn + n * Nn + m] = acc[i][j];
        }
}
__global__ void scores_reduce_kernel(const float* part, float* scores) {
    int nm = blockIdx.x * 256 + threadIdx.x;
    if (nm >= Nn * Nn) return;
    float s = 0.f;
    for (int b = 0; b < Bb; b++) s += part[(size_t)b * Nn * Nn + nm];
    scores[nm] = s;
}

__global__ void mlin_kernel(const float* scores, const float* wlin, const float* blin,
                            const float* vmat, float* Mout) {
    int n = blockIdx.x;
    __shared__ float srow[Nn];
    if (threadIdx.x < Nn) srow[threadIdx.x] = scores[n * Nn + threadIdx.x];
    __syncthreads();
    int j = threadIdx.x;
    if (j < Nn) {
        float acc = blin[j];
        for (int m = 0; m < Nn; m++) acc += srow[m] * wlin[j * Nn + m];
        Mout[n * Nn + j] = vmat[n * Nn + j] + tanhf(acc);
    }
}

__global__ void topk_kernel(const float* M, float* vout, int* iout) {
    int mode = blockIdx.x, t = threadIdx.x;
    if (t >= Nn) return;
    float p[Nn], mx = -1e30f;
    for (int i = 0; i < Nn; i++) {
        float v = (mode == 0) ? M[t * Nn + i] : M[i * Nn + t];
        p[i] = v; mx = fmaxf(mx, v);
    }
    float sum = 0.f;
    for (int i = 0; i < Nn; i++) { p[i] = expf(p[i] - mx); sum += p[i]; }
    float inv = 1.f / sum;
    for (int i = 0; i < Nn; i++) p[i] *= inv;
    for (int k = 0; k < TOPKv; k++) {
        float bv = -1.f; int bi = 0;
        for (int i = 0; i < Nn; i++) if (p[i] > bv) { bv = p[i]; bi = i; }
        vout[mode * Nn * TOPKv + t * TOPKv + k] = bv;
        iout[mode * Nn * TOPKv + t * TOPKv + k] = bi;
        p[bi] = -2.f;
    }
}

// ---------------- fusion + LayerNorm ----------------
__global__ __launch_bounds__(256)
void fusion_kernel(const float* base, const float* gath, const float* vsel, const int* isel,
                   const float* ln_g, const float* ln_b, float* s1_out, float* out, int rowOff) {
    int n = blockIdx.x, b = blockIdx.y, tid = threadIdx.x;
    __shared__ float sv[TOPKv];
    __shared__ int si[TOPKv];
    if (tid < TOPKv) { sv[tid] = vsel[n * TOPKv + tid]; si[tid] = isel[n * TOPKv + tid]; }
    __syncthreads();
    size_t rbase = (size_t)(b * Nn + n) * Dd;
    float x[8];
    #pragma unroll
    for (int i = 0; i < 8; i++) x[i] = base[rbase + i * 256 + tid];
    for (int k = 0; k < TOPKv; k++) {
        float w = sv[k];
        const float* gp = gath + (size_t)(b * Nn + si[k]) * Dd + tid;
        #pragma unroll
        for (int i = 0; i < 8; i++) x[i] += w * gp[i * 256];
    }
    if (s1_out)
        #pragma unroll
        for (int i = 0; i < 8; i++) s1_out[rbase + i * 256 + tid] = x[i];
    float s = 0.f, ss = 0.f;
    #pragma unroll
    for (int i = 0; i < 8; i++) { s += x[i]; ss += x[i] * x[i]; }
    s = blockReduceSum(s); ss = blockReduceSum(ss);
    float mean = s * (1.f / Dd);
    float var = fmaxf((ss - s * mean) * (1.f / (Dd - 1)), 0.f);
    float inv = 1.f / (sqrtf(var) + 1e-6f);
    size_t ob = (size_t)(b * (2 * Nn) + rowOff + n) * Dd;
    #pragma unroll
    for (int i = 0; i < 8; i++) {
        int d = i * 256 + tid;
        out[ob + d] = ln_g[d] * (x[i] - mean) * inv + ln_b[d];
    }
}

// ---------------- host ----------------
extern "C" void kernel_launch(void* const* d_in, const int* in_sizes, int n_in,
                              void* d_out, int out_size)
{
    const float *src1=(const float*)d_in[0], *src2=(const float*)d_in[1];
    const float *w0a=(const float*)d_in[2], *b0a=(const float*)d_in[3];
    const float *g0a=(const float*)d_in[4], *be0a=(const float*)d_in[5];
    const float *w0b=(const float*)d_in[6], *b0b=(const float*)d_in[7];
    const float *g0b=(const float*)d_in[8], *be0b=(const float*)d_in[9];
    const float *w1a=(const float*)d_in[10], *b1a=(const float*)d_in[11];
    const float *g1a=(const float*)d_in[12], *be1a=(const float*)d_in[13];
    const float *w1b=(const float*)d_in[14], *b1b=(const float*)d_in[15];
    const float *g1b=(const float*)d_in[16], *be1b=(const float*)d_in[17];
    const float *wlin=(const float*)d_in[18], *blin=(const float*)d_in[19];
    const float *ln_g=(const float*)d_in[20], *ln_b=(const float*)d_in[21];
    const float *vmat=(const float*)d_in[22];
    float* out = (float*)d_out;

    void* p;
    #define SYM(s,v,t) cudaGetSymbolAddress(&p,s); t v=(t)p;
    SYM(g_x1e,x1e,bf16*) SYM(g_x2e,x2e,bf16*)
    SYM(g_w0ae,w0ae,bf16*) SYM(g_w1ae,w1ae,bf16*)
    SYM(g_w0be,w0be,bf16*) SYM(g_w1be,w1be,bf16*)
    SYM(g_h1ae,h1ae,bf16*) SYM(g_h1be,h1be,bf16*)
    SYM(g_h2a,h2a,float*) SYM(g_h2b,h2b,float*) SYM(g_s1,s1,float*)
    SYM(g_part,part,float*) SYM(g_scores,scores,float*) SYM(g_M,Mbuf,float*)
    SYM(g_bnsc,bnsc,float*) SYM(g_bnsh,bnsh,float*) SYM(g_rowsum,rsum,float*)
    SYM(g_topv,topv,float*) SYM(g_topi,topi,int*)
    #undef SYM

    cudaFuncSetAttribute(hmma_gemm, cudaFuncAttributeMaxDynamicSharedMemorySize, 98304);

    // ext conversions: A-kind = [hi|hi|lo], B-kind = [hi|lo|hi]
    int n4 = ROWS * Dd / 4;
    cvt_ext<<<(n4+255)/256, 256>>>(src1, x1e, Dd/4, n4, 1);
    cvt_ext<<<(n4+255)/256, 256>>>(src2, x2e, Dd/4, n4, 1);
    n4 = H1v * Dd / 4;
    cvt_ext<<<(n4+255)/256, 256>>>(w0a, w0ae, Dd/4, n4, 0);
    cvt_ext<<<(n4+255)/256, 256>>>(w1a, w1ae, Dd/4, n4, 0);
    n4 = H2v * H1v / 4;
    cvt_ext<<<(n4+255)/256, 256>>>(w0b, w0be, H1v/4, n4, 0);
    cvt_ext<<<(n4+255)/256, 256>>>(w1b, w1be, H1v/4, n4, 0);

    rowsum_kernel<<<dim3(H2v,2), 256>>>(w0b, w1b, H1v, rsum);

    // GEMM1: K' = 3*2048 = 6144, 96 chunks; h1 written in ext layout
    GArgs a0 = { x1e, w0ae, b0a, 0, 0, 0, 0, h1ae };
    GArgs a1 = { x2e, w1ae, b1a, 0, 0, 0, 0, h1be };
    hmma_gemm<<<dim3(H1v/128, ROWS/128, 2), 256, 98304>>>(a0, a1, H1v, 3*Dd, 3*Dd/64, 0);

    bnstats_ext<<<dim3(Nn,2), 256>>>(h1ae, h1be, H1v, g0a, be0a, g1a, be1a, bnsc, bnsh);

    // GEMM2: K' = 3*1024 = 3072, 48 chunks; fp32 out with folded BN affine
    GArgs c0 = { h1ae, w0be, b0b, bnsc,    bnsh,    rsum,      h2a, 0 };
    GArgs c1 = { h1be, w1be, b1b, bnsc+Nn, bnsh+Nn, rsum+H2v,  h2b, 0 };
    hmma_gemm<<<dim3(H2v/128, ROWS/128, 2), 256, 98304>>>(c0, c1, H2v, 3*H1v, 3*H1v/64, 1);

    bnstats_f32<<<dim3(Nn,2), 256>>>(h2a, h2b, H2v, g0b, be0b, g1b, be1b, bnsc+2*Nn, bnsh+2*Nn);

    scores_part_kernel<<<Bb, 256>>>(h2a, h2b, bnsc, bnsh, part);
    scores_reduce_kernel<<<(Nn*Nn+255)/256, 256>>>(part, scores);
    mlin_kernel<<<Nn, 64>>>(scores, wlin, blin, vmat, Mbuf);
    topk_kernel<<<2, 64>>>(Mbuf, topv, topi);

    fusion_kernel<<<dim3(Nn,Bb), 256>>>(src1, src2, topv, topi, ln_g, ln_b, s1, out, 0);
    fusion_kernel<<<dim3(Nn,Bb), 256>>>(src2, s1, topv+Nn*TOPKv, topi+Nn*TOPKv, ln_g, ln_b, 0, out, Nn);
}